// round 14
// baseline (speedup 1.0000x reference)
#include <cuda_runtime.h>
#include <cstdint>
#include <cmath>

#define B_SZ   64
#define KCP    16
#define NDIM   19            // K + 3
#define NPAD   20            // padded coeff rows per batch (16B alignment)
#define HH     512
#define WW     512
#define HWPIX  (HH * WW)
#define PAIRS  (HWPIX / 2)   // 131072 pixel pairs, 1 per thread

// inv_delta[:, :16] passed by value (computed on host — input-independent).
struct InvW {
    float w[NDIM][KCP];
};

// ---------------------------------------------------------------------------
// Packed f32x2 helpers (sm_103a).
// ---------------------------------------------------------------------------
__device__ __forceinline__ unsigned long long pack2(float lo, float hi) {
    unsigned long long r;
    asm("mov.b64 %0, {%1, %2};" : "=l"(r) : "f"(lo), "f"(hi));
    return r;
}
__device__ __forceinline__ unsigned long long fma2(unsigned long long a,
                                                   unsigned long long b,
                                                   unsigned long long c) {
    unsigned long long d;
    asm("fma.rn.f32x2 %0, %1, %2, %3;" : "=l"(d) : "l"(a), "l"(b), "l"(c));
    return d;
}
__device__ __forceinline__ unsigned long long add2(unsigned long long a,
                                                   unsigned long long b) {
    unsigned long long d;
    asm("add.rn.f32x2 %0, %1, %2;" : "=l"(d) : "l"(a), "l"(b));
    return d;
}

// ---------------------------------------------------------------------------
// Pipelined kernel: half-batch register double-buffer gives every LDS ~20
// issue slots of cover before first use. (256,2) -> 128-reg budget, no spills.
// Coeff slot map per batch (float2 = (cx_i, cy_i)):
//   ull2[0..4]  = rows 0..9   (RBF k0..k9)
//   ull2[5..7]  = rows 10..15 (RBF k10..k15)
//   ull2[8]     = rows 16 (const), 17 (X)
//   ull2[9]     = rows 18 (Y), 19 (pad)
// ---------------------------------------------------------------------------
__global__ void __launch_bounds__(256, 2) tps_fused_kernel(
    InvW inv, const float* __restrict__ sp, ulonglong2* __restrict__ out) {

    __shared__ __align__(16) float2 s_coeff[B_SZ * NPAD];  // 10 KB
    __shared__ __align__(16) float s_w[NDIM][KCP];         // 1.2 KB

    const int tid = threadIdx.x;

    // Stage invW into shared (304 floats = 76 float4; one-shot).
    {
        const float4* wsrc = reinterpret_cast<const float4*>(&inv.w[0][0]);
        float4* wdst = reinterpret_cast<float4*>(&s_w[0][0]);
        if (tid < (NDIM * KCP) / 4) wdst[tid] = wsrc[tid];
    }
    __syncthreads();

    // Coeff prologue: thread t -> batch b = t&63, row-group q = t>>6 (warp-
    // uniform). Rows i = q + 4m, m = 0..4 (q=3,m=4 -> pad row 19).
    {
        const int b = tid & 63;
        const int q = tid >> 6;
        const float2* spb = reinterpret_cast<const float2*>(sp) + b * KCP;
        float accx[5] = {0.f, 0.f, 0.f, 0.f, 0.f};
        float accy[5] = {0.f, 0.f, 0.f, 0.f, 0.f};
        #pragma unroll
        for (int j = 0; j < KCP; j++) {
            const float2 s = spb[j];                 // LDG.64 (L2-resident)
            #pragma unroll
            for (int m = 0; m < 5; m++) {
                const int i = q + 4 * m;
                if (i < NDIM) {
                    const float w = s_w[i][j];       // broadcast LDS
                    accx[m] = fmaf(w, s.x, accx[m]);
                    accy[m] = fmaf(w, s.y, accy[m]);
                }
            }
        }
        #pragma unroll
        for (int m = 0; m < 5; m++) {
            const int i = q + 4 * m;
            s_coeff[b * NPAD + i] =
                (i < NDIM) ? make_float2(accx[m], accy[m]) : make_float2(0.f, 0.f);
        }
    }
    __syncthreads();

    // ---- per-thread pixel pair ----
    const int t  = blockIdx.x * 256 + tid;
    const int n0 = t * 2;
    const int w0 = n0 & (WW - 1);
    const int h  = n0 >> 9;
    const float X0 = fmaf((float)w0, 2.0f / (float)(WW - 1), -1.0f);
    const float X1 = X0 + 2.0f / (float)(WW - 1);
    const float Y  = fmaf((float)h, 2.0f / (float)(HH - 1), -1.0f);

    unsigned long long u0[KCP], u1[KCP];
    #pragma unroll
    for (int k = 0; k < KCP; k++) {
        const float cx = -1.0f + (float)(k >> 2) * (2.0f / 3.0f);
        const float cy = -1.0f + (float)(k & 3) * (2.0f / 3.0f);
        const float dy  = Y - cy;
        const float dy2 = dy * dy;
        {
            float dx = X0 - cx;
            float r2 = fmaf(dx, dx, dy2);
            float u  = r2 * __logf(r2 + 1e-6f);
            u0[k] = pack2(u, u);
        }
        {
            float dx = X1 - cx;
            float r2 = fmaf(dx, dx, dy2);
            float u  = r2 * __logf(r2 + 1e-6f);
            u1[k] = pack2(u, u);
        }
    }
    const unsigned long long X0d  = pack2(X0, X0);
    const unsigned long long X1d  = pack2(X1, X1);
    const unsigned long long Yd   = pack2(Y, Y);
    const unsigned long long ONEd = pack2(1.0f, 1.0f);

    // ---- pipelined main loop ----
    const ulonglong2* cbase = reinterpret_cast<const ulonglong2*>(s_coeff);

    ulonglong2 P[5], Q[5];
    #pragma unroll
    for (int i = 0; i < 5; i++) P[i] = cbase[i];          // batch 0, half 0

    #pragma unroll 2
    for (int b = 0; b < B_SZ; b++) {
        // Prefetch half 1 of this batch.
        #pragma unroll
        for (int i = 0; i < 5; i++) Q[i] = cbase[b * 10 + 5 + i];

        // Compute half 0 (RBF rows 0..9) from P — covers Q's LDS latency.
        unsigned long long a0 = 0ULL, b0 = 0ULL, a1 = 0ULL, b1 = 0ULL;
        #pragma unroll
        for (int j = 0; j < 5; j++) {
            a0 = fma2(u0[2 * j + 0], P[j].x, a0);
            b0 = fma2(u0[2 * j + 1], P[j].y, b0);
            a1 = fma2(u1[2 * j + 0], P[j].x, a1);
            b1 = fma2(u1[2 * j + 1], P[j].y, b1);
        }

        // Prefetch half 0 of the next batch (wraps harmlessly at b=63).
        const int bn = (b + 1) & (B_SZ - 1);
        #pragma unroll
        for (int i = 0; i < 5; i++) P[i] = cbase[bn * 10 + i];

        // Compute half 1 (RBF rows 10..15 + affine) from Q.
        #pragma unroll
        for (int j = 0; j < 3; j++) {
            a0 = fma2(u0[10 + 2 * j], Q[j].x, a0);
            b0 = fma2(u0[11 + 2 * j], Q[j].y, b0);
            a1 = fma2(u1[10 + 2 * j], Q[j].x, a1);
            b1 = fma2(u1[11 + 2 * j], Q[j].y, b1);
        }
        a0 = fma2(ONEd, Q[3].x, a0);   // + row16 (const)
        a0 = fma2(X0d,  Q[3].y, a0);   // + X * row17
        b0 = fma2(Yd,   Q[4].x, b0);   // + Y * row18
        a1 = fma2(ONEd, Q[3].x, a1);
        a1 = fma2(X1d,  Q[3].y, a1);
        b1 = fma2(Yd,   Q[4].x, b1);

        ulonglong2 r;
        r.x = add2(a0, b0);
        r.y = add2(a1, b1);
        out[(size_t)b * PAIRS + t] = r;               // STG.128
    }
}

// ---------------------------------------------------------------------------
// Host: build delta(19x19), invert (Gauss-Jordan, partial pivoting, fp64).
// Input-independent -> runs on CPU at capture time; rides in as kernel param.
// ---------------------------------------------------------------------------
static inline double h_cpx(int k) { return -1.0 + (double)(k >> 2) * (2.0 / 3.0); }
static inline double h_cpy(int k) { return -1.0 + (double)(k & 3) * (2.0 / 3.0); }

static void build_invw(InvW* out) {
    double M[NDIM][2 * NDIM];
    for (int r = 0; r < NDIM; r++)
        for (int c = 0; c < 2 * NDIM; c++) {
            double v = 0.0;
            if (c >= NDIM) {
                v = (c - NDIM == r) ? 1.0 : 0.0;
            } else if (r < KCP && c < KCP) {
                double dx = h_cpx(r) - h_cpx(c);
                double dy = h_cpy(r) - h_cpy(c);
                double r2 = dx * dx + dy * dy;
                v = r2 * log(r2 + 1e-6);
            } else if (r < KCP) {
                v = (c == KCP) ? 1.0 : ((c == KCP + 1) ? h_cpx(r) : h_cpy(r));
            } else if (c < KCP) {
                v = (r == KCP) ? 1.0 : ((r == KCP + 1) ? h_cpx(c) : h_cpy(c));
            }
            M[r][c] = v;
        }

    for (int p = 0; p < NDIM; p++) {
        int best = p;
        double bm = fabs(M[p][p]);
        for (int r = p + 1; r < NDIM; r++) {
            double m = fabs(M[r][p]);
            if (m > bm) { bm = m; best = r; }
        }
        if (best != p)
            for (int c = 0; c < 2 * NDIM; c++) {
                double tv = M[p][c]; M[p][c] = M[best][c]; M[best][c] = tv;
            }
        const double inv = 1.0 / M[p][p];
        for (int c = 0; c < 2 * NDIM; c++) M[p][c] *= inv;
        for (int r = 0; r < NDIM; r++) {
            if (r == p) continue;
            const double f = M[r][p];
            if (f == 0.0) continue;
            for (int c = 0; c < 2 * NDIM; c++) M[r][c] -= f * M[p][c];
        }
    }

    for (int i = 0; i < NDIM; i++)
        for (int j = 0; j < KCP; j++)
            out->w[i][j] = (float)M[i][NDIM + j];
}

// ---------------------------------------------------------------------------
extern "C" void kernel_launch(void* const* d_in, const int* in_sizes, int n_in,
                              void* d_out, int out_size) {
    const float* sp = (const float*)d_in[0];        // [64, 16, 2] fp32
    ulonglong2* out = (ulonglong2*)d_out;           // [64, 512, 512, 2] fp32

    InvW inv;
    build_invw(&inv);                               // host-side, capture-time only

    tps_fused_kernel<<<PAIRS / 256, 256>>>(inv, sp, out);
}

// round 15
// speedup vs baseline: 1.5535x; 1.5535x over previous
#include <cuda_runtime.h>
#include <cstdint>
#include <cmath>

#define B_SZ   64
#define KCP    16
#define NDIM   19            // K + 3
#define NPAD   20            // padded coeff rows per batch (16B alignment)
#define HH     512
#define WW     512
#define HWPIX  (HH * WW)
#define PAIRS  (HWPIX / 2)   // 131072 output ulonglong2 per batch
#define NTHREADS_TOTAL (HWPIX / 4)   // 65536 threads, 4 pixels each

// inv_delta[:, :16] passed by value (computed on host — input-independent).
struct InvW {
    float w[NDIM][KCP];
};

// ---------------------------------------------------------------------------
// Packed f32x2 helpers (sm_103a).
// ---------------------------------------------------------------------------
__device__ __forceinline__ unsigned long long pack2(float lo, float hi) {
    unsigned long long r;
    asm("mov.b64 %0, {%1, %2};" : "=l"(r) : "f"(lo), "f"(hi));
    return r;
}
// Duplicate one scalar into both lanes (single ALU op at point of use).
__device__ __forceinline__ unsigned long long dupf(float v) {
    unsigned long long r;
    asm("mov.b64 %0, {%1, %1};" : "=l"(r) : "f"(v));
    return r;
}
__device__ __forceinline__ unsigned long long fma2(unsigned long long a,
                                                   unsigned long long b,
                                                   unsigned long long c) {
    unsigned long long d;
    asm("fma.rn.f32x2 %0, %1, %2, %3;" : "=l"(d) : "l"(a), "l"(b), "l"(c));
    return d;
}

// ---------------------------------------------------------------------------
// 4-pixels-per-thread kernel. Crossbar traffic per pixel is halved vs the
// 2-px kernels: 10 broadcast LDS.128 per warp-batch now serve 4 pixels.
// Basis kept SCALAR in registers (64 floats), lane-duplicated on the fly
// (ALU pipe, parallel to FMA). Grid = 256 blocks -> ONE wave at occ 2.
// ---------------------------------------------------------------------------
__global__ void __launch_bounds__(256, 2) tps_fused_kernel(
    InvW inv, const float* __restrict__ sp, ulonglong2* __restrict__ out) {

    __shared__ __align__(16) float2 s_coeff[B_SZ * NPAD];  // 10 KB
    __shared__ __align__(16) float s_w[NDIM][KCP];         // 1.2 KB

    const int tid = threadIdx.x;

    // Stage invW into shared (304 floats = 76 float4; one-shot).
    {
        const float4* wsrc = reinterpret_cast<const float4*>(&inv.w[0][0]);
        float4* wdst = reinterpret_cast<float4*>(&s_w[0][0]);
        if (tid < (NDIM * KCP) / 4) wdst[tid] = wsrc[tid];
    }
    __syncthreads();

    // Coeff prologue: thread t -> batch b = t&63, row-group q = t>>6 (warp-
    // uniform). Rows i = q + 4m, m = 0..4 (q=3,m=4 -> pad row 19).
    {
        const int b = tid & 63;
        const int q = tid >> 6;
        const float2* spb = reinterpret_cast<const float2*>(sp) + b * KCP;
        float accx[5] = {0.f, 0.f, 0.f, 0.f, 0.f};
        float accy[5] = {0.f, 0.f, 0.f, 0.f, 0.f};
        #pragma unroll
        for (int j = 0; j < KCP; j++) {
            const float2 s = spb[j];                 // LDG.64 (L2-resident)
            #pragma unroll
            for (int m = 0; m < 5; m++) {
                const int i = q + 4 * m;
                if (i < NDIM) {
                    const float w = s_w[i][j];       // broadcast LDS
                    accx[m] = fmaf(w, s.x, accx[m]);
                    accy[m] = fmaf(w, s.y, accy[m]);
                }
            }
        }
        #pragma unroll
        for (int m = 0; m < 5; m++) {
            const int i = q + 4 * m;
            s_coeff[b * NPAD + i] =
                (i < NDIM) ? make_float2(accx[m], accy[m]) : make_float2(0.f, 0.f);
        }
    }
    __syncthreads();

    // ---- per-thread 4-pixel strip (same row; 512 % 4 == 0) ----
    const int g  = blockIdx.x * 256 + tid;      // 0..65535
    const int n0 = g * 4;
    const int w0 = n0 & (WW - 1);
    const int h  = n0 >> 9;
    const float Y  = fmaf((float)h, 2.0f / (float)(HH - 1), -1.0f);
    const float DX = 2.0f / (float)(WW - 1);
    float X[4];
    #pragma unroll
    for (int p = 0; p < 4; p++) X[p] = fmaf((float)(w0 + p), DX, -1.0f);

    // Scalar RBF basis: v[p][k], 64 registers.
    float v[4][KCP];
    #pragma unroll
    for (int k = 0; k < KCP; k++) {
        const float cx = -1.0f + (float)(k >> 2) * (2.0f / 3.0f);
        const float cy = -1.0f + (float)(k & 3) * (2.0f / 3.0f);
        const float dy  = Y - cy;
        const float dy2 = dy * dy;
        #pragma unroll
        for (int p = 0; p < 4; p++) {
            const float dx = X[p] - cx;
            const float r2 = fmaf(dx, dx, dy2);
            v[p][k] = r2 * __logf(r2 + 1e-6f);
        }
    }

    // Persistent lane-duplicated affine terms.
    unsigned long long Xd[4];
    #pragma unroll
    for (int p = 0; p < 4; p++) Xd[p] = dupf(X[p]);
    const unsigned long long Yd = dupf(Y);

    // ---- main loop: 64 batches; 10 broadcast LDS.128 serve 4 pixels ----
    #pragma unroll 2
    for (int b = 0; b < B_SZ; b++) {
        const ulonglong2* cc = reinterpret_cast<const ulonglong2*>(s_coeff + b * NPAD);

        // Affine: rows 16 (const), 17 (X), 18 (Y).
        const ulonglong2 c8 = cc[8];           // rows 16, 17
        const ulonglong2 c9 = cc[9];           // rows 18, pad
        unsigned long long acc[4];
        #pragma unroll
        for (int p = 0; p < 4; p++) {
            acc[p] = fma2(Xd[p], c8.y, c8.x);  // row16 + X*row17
            acc[p] = fma2(Yd,    c9.x, acc[p]);
        }

        // RBF rows 0..15.
        #pragma unroll
        for (int j = 0; j < 8; j++) {
            const ulonglong2 c = cc[j];        // rows 2j, 2j+1 (broadcast LDS.128)
            #pragma unroll
            for (int p = 0; p < 4; p++) {
                acc[p] = fma2(dupf(v[p][2 * j + 0]), c.x, acc[p]);
                acc[p] = fma2(dupf(v[p][2 * j + 1]), c.y, acc[p]);
            }
        }

        ulonglong2 r0, r1;
        r0.x = acc[0]; r0.y = acc[1];
        r1.x = acc[2]; r1.y = acc[3];
        const size_t base = (size_t)b * PAIRS + 2 * g;
        out[base]     = r0;                    // STG.128
        out[base + 1] = r1;                    // STG.128
    }
}

// ---------------------------------------------------------------------------
// Host: build delta(19x19), invert (Gauss-Jordan, partial pivoting, fp64).
// Input-independent -> runs on CPU at capture time; rides in as kernel param.
// ---------------------------------------------------------------------------
static inline double h_cpx(int k) { return -1.0 + (double)(k >> 2) * (2.0 / 3.0); }
static inline double h_cpy(int k) { return -1.0 + (double)(k & 3) * (2.0 / 3.0); }

static void build_invw(InvW* out) {
    double M[NDIM][2 * NDIM];
    for (int r = 0; r < NDIM; r++)
        for (int c = 0; c < 2 * NDIM; c++) {
            double v = 0.0;
            if (c >= NDIM) {
                v = (c - NDIM == r) ? 1.0 : 0.0;
            } else if (r < KCP && c < KCP) {
                double dx = h_cpx(r) - h_cpx(c);
                double dy = h_cpy(r) - h_cpy(c);
                double r2 = dx * dx + dy * dy;
                v = r2 * log(r2 + 1e-6);
            } else if (r < KCP) {
                v = (c == KCP) ? 1.0 : ((c == KCP + 1) ? h_cpx(r) : h_cpy(r));
            } else if (c < KCP) {
                v = (r == KCP) ? 1.0 : ((r == KCP + 1) ? h_cpx(c) : h_cpy(c));
            }
            M[r][c] = v;
        }

    for (int p = 0; p < NDIM; p++) {
        int best = p;
        double bm = fabs(M[p][p]);
        for (int r = p + 1; r < NDIM; r++) {
            double m = fabs(M[r][p]);
            if (m > bm) { bm = m; best = r; }
        }
        if (best != p)
            for (int c = 0; c < 2 * NDIM; c++) {
                double tv = M[p][c]; M[p][c] = M[best][c]; M[best][c] = tv;
            }
        const double inv = 1.0 / M[p][p];
        for (int c = 0; c < 2 * NDIM; c++) M[p][c] *= inv;
        for (int r = 0; r < NDIM; r++) {
            if (r == p) continue;
            const double f = M[r][p];
            if (f == 0.0) continue;
            for (int c = 0; c < 2 * NDIM; c++) M[r][c] -= f * M[p][c];
        }
    }

    for (int i = 0; i < NDIM; i++)
        for (int j = 0; j < KCP; j++)
            out->w[i][j] = (float)M[i][NDIM + j];
}

// ---------------------------------------------------------------------------
extern "C" void kernel_launch(void* const* d_in, const int* in_sizes, int n_in,
                              void* d_out, int out_size) {
    const float* sp = (const float*)d_in[0];        // [64, 16, 2] fp32
    ulonglong2* out = (ulonglong2*)d_out;           // [64, 512, 512, 2] fp32

    InvW inv;
    build_invw(&inv);                               // host-side, capture-time only

    tps_fused_kernel<<<NTHREADS_TOTAL / 256, 256>>>(inv, sp, out);
}

// round 16
// speedup vs baseline: 1.7352x; 1.1170x over previous
#include <cuda_runtime.h>
#include <cstdint>
#include <cmath>

#define B_SZ   64
#define KCP    16
#define NDIM   19            // K + 3
#define NPAD   20            // padded coeff rows per batch (16B alignment)
#define HH     512
#define WW     512
#define HWPIX  (HH * WW)
#define PAIRS  (HWPIX / 2)   // 131072 pixel pairs, 1 per thread
#define TPB    128           // threads per block
#define NBLK   (PAIRS / TPB) // 1024 blocks -> one wave at 7 blocks/SM

// inv_delta[:, :16] passed by value (computed on host — input-independent).
struct InvW {
    float w[NDIM][KCP];
};

// ---------------------------------------------------------------------------
// Packed f32x2 helpers (sm_103a).
// ---------------------------------------------------------------------------
__device__ __forceinline__ unsigned long long dupf(float v) {
    // Folded into the FFMA2 operand path by ptxas (measured: no alu cost).
    unsigned long long r;
    asm("mov.b64 %0, {%1, %1};" : "=l"(r) : "f"(v));
    return r;
}
__device__ __forceinline__ unsigned long long fma2(unsigned long long a,
                                                   unsigned long long b,
                                                   unsigned long long c) {
    unsigned long long d;
    asm("fma.rn.f32x2 %0, %1, %2, %3;" : "=l"(d) : "l"(a), "l"(b), "l"(c));
    return d;
}
__device__ __forceinline__ unsigned long long add2(unsigned long long a,
                                                   unsigned long long b) {
    unsigned long long d;
    asm("add.rn.f32x2 %0, %1, %2;" : "=l"(d) : "l"(a), "l"(b));
    return d;
}

// ---------------------------------------------------------------------------
// 128-thread blocks, 7/SM, one 1024-block wave. 2 pixels/thread, scalar
// basis (32 regs) lane-duplicated at use (free), 4 accumulator chains.
// Per batch: 10 broadcast LDS.128 + 42 fma2 + 2 add2 + 1 STG.128.
// ---------------------------------------------------------------------------
__global__ void __launch_bounds__(TPB, 7) tps_fused_kernel(
    InvW inv, const float* __restrict__ sp, ulonglong2* __restrict__ out) {

    __shared__ __align__(16) float2 s_coeff[B_SZ * NPAD];  // 10 KB
    __shared__ __align__(16) float s_w[NDIM][KCP];         // 1.2 KB

    const int tid = threadIdx.x;

    // Stage invW into shared (304 floats = 76 float4; one-shot).
    {
        const float4* wsrc = reinterpret_cast<const float4*>(&inv.w[0][0]);
        float4* wdst = reinterpret_cast<float4*>(&s_w[0][0]);
        if (tid < (NDIM * KCP) / 4) wdst[tid] = wsrc[tid];
    }
    __syncthreads();

    // Coeff prologue: 128 threads -> b = tid&63, half q = tid>>6 (warp-
    // uniform). Rows i = q + 2m, m = 0..9 (i==19 -> pad zeros).
    {
        const int b = tid & 63;
        const int q = tid >> 6;
        const float2* spb = reinterpret_cast<const float2*>(sp) + b * KCP;
        float accx[10], accy[10];
        #pragma unroll
        for (int m = 0; m < 10; m++) { accx[m] = 0.0f; accy[m] = 0.0f; }
        #pragma unroll
        for (int j = 0; j < KCP; j++) {
            const float2 s = spb[j];                 // LDG.64 (L2-resident)
            #pragma unroll
            for (int m = 0; m < 10; m++) {
                const int i = q + 2 * m;
                if (i < NDIM) {
                    const float w = s_w[i][j];       // broadcast LDS
                    accx[m] = fmaf(w, s.x, accx[m]);
                    accy[m] = fmaf(w, s.y, accy[m]);
                }
            }
        }
        #pragma unroll
        for (int m = 0; m < 10; m++) {
            const int i = q + 2 * m;
            s_coeff[b * NPAD + i] =
                (i < NDIM) ? make_float2(accx[m], accy[m]) : make_float2(0.f, 0.f);
        }
    }
    __syncthreads();

    // ---- per-thread pixel pair ----
    const int t  = blockIdx.x * TPB + tid;
    const int n0 = t * 2;
    const int w0 = n0 & (WW - 1);
    const int h  = n0 >> 9;
    const float X0 = fmaf((float)w0, 2.0f / (float)(WW - 1), -1.0f);
    const float X1 = X0 + 2.0f / (float)(WW - 1);
    const float Y  = fmaf((float)h, 2.0f / (float)(HH - 1), -1.0f);

    // Scalar RBF basis (32 registers).
    float v0[KCP], v1[KCP];
    #pragma unroll
    for (int k = 0; k < KCP; k++) {
        const float cx = -1.0f + (float)(k >> 2) * (2.0f / 3.0f);
        const float cy = -1.0f + (float)(k & 3) * (2.0f / 3.0f);
        const float dy  = Y - cy;
        const float dy2 = dy * dy;
        {
            float dx = X0 - cx;
            float r2 = fmaf(dx, dx, dy2);
            v0[k] = r2 * __logf(r2 + 1e-6f);
        }
        {
            float dx = X1 - cx;
            float r2 = fmaf(dx, dx, dy2);
            v1[k] = r2 * __logf(r2 + 1e-6f);
        }
    }

    // ---- main loop: 64 batches ----
    #pragma unroll 2
    for (int b = 0; b < B_SZ; b++) {
        const ulonglong2* cc = reinterpret_cast<const ulonglong2*>(s_coeff + b * NPAD);
        // Affine: rows 16 (const), 17 (X), 18 (Y).
        const ulonglong2 c8 = cc[8];   // rows 16, 17
        const ulonglong2 c9 = cc[9];   // rows 18, pad
        unsigned long long a0 = fma2(dupf(X0), c8.y, c8.x);
        unsigned long long a1 = fma2(dupf(X1), c8.y, c8.x);
        a0 = fma2(dupf(Y), c9.x, a0);
        a1 = fma2(dupf(Y), c9.x, a1);
        unsigned long long b0 = 0ULL, b1 = 0ULL;
        #pragma unroll
        for (int j = 0; j < 8; j++) {
            const ulonglong2 c = cc[j];           // rows 2j, 2j+1 (broadcast LDS.128)
            a0 = fma2(dupf(v0[2 * j + 0]), c.x, a0);
            b0 = fma2(dupf(v0[2 * j + 1]), c.y, b0);
            a1 = fma2(dupf(v1[2 * j + 0]), c.x, a1);
            b1 = fma2(dupf(v1[2 * j + 1]), c.y, b1);
        }
        ulonglong2 r;
        r.x = add2(a0, b0);
        r.y = add2(a1, b1);
        out[(size_t)b * PAIRS + t] = r;           // STG.128
    }
}

// ---------------------------------------------------------------------------
// Host: build delta(19x19), invert (Gauss-Jordan, partial pivoting, fp64).
// Input-independent -> runs on CPU at capture time; rides in as kernel param.
// ---------------------------------------------------------------------------
static inline double h_cpx(int k) { return -1.0 + (double)(k >> 2) * (2.0 / 3.0); }
static inline double h_cpy(int k) { return -1.0 + (double)(k & 3) * (2.0 / 3.0); }

static void build_invw(InvW* out) {
    double M[NDIM][2 * NDIM];
    for (int r = 0; r < NDIM; r++)
        for (int c = 0; c < 2 * NDIM; c++) {
            double v = 0.0;
            if (c >= NDIM) {
                v = (c - NDIM == r) ? 1.0 : 0.0;
            } else if (r < KCP && c < KCP) {
                double dx = h_cpx(r) - h_cpx(c);
                double dy = h_cpy(r) - h_cpy(c);
                double r2 = dx * dx + dy * dy;
                v = r2 * log(r2 + 1e-6);
            } else if (r < KCP) {
                v = (c == KCP) ? 1.0 : ((c == KCP + 1) ? h_cpx(r) : h_cpy(r));
            } else if (c < KCP) {
                v = (r == KCP) ? 1.0 : ((r == KCP + 1) ? h_cpx(c) : h_cpy(c));
            }
            M[r][c] = v;
        }

    for (int p = 0; p < NDIM; p++) {
        int best = p;
        double bm = fabs(M[p][p]);
        for (int r = p + 1; r < NDIM; r++) {
            double m = fabs(M[r][p]);
            if (m > bm) { bm = m; best = r; }
        }
        if (best != p)
            for (int c = 0; c < 2 * NDIM; c++) {
                double tv = M[p][c]; M[p][c] = M[best][c]; M[best][c] = tv;
            }
        const double inv = 1.0 / M[p][p];
        for (int c = 0; c < 2 * NDIM; c++) M[p][c] *= inv;
        for (int r = 0; r < NDIM; r++) {
            if (r == p) continue;
            const double f = M[r][p];
            if (f == 0.0) continue;
            for (int c = 0; c < 2 * NDIM; c++) M[r][c] -= f * M[p][c];
        }
    }

    for (int i = 0; i < NDIM; i++)
        for (int j = 0; j < KCP; j++)
            out->w[i][j] = (float)M[i][NDIM + j];
}

// ---------------------------------------------------------------------------
extern "C" void kernel_launch(void* const* d_in, const int* in_sizes, int n_in,
                              void* d_out, int out_size) {
    const float* sp = (const float*)d_in[0];        // [64, 16, 2] fp32
    ulonglong2* out = (ulonglong2*)d_out;           // [64, 512, 512, 2] fp32

    InvW inv;
    build_invw(&inv);                               // host-side, capture-time only

    tps_fused_kernel<<<NBLK, TPB>>>(inv, sp, out);
}